// round 10
// baseline (speedup 1.0000x reference)
#include <cuda_runtime.h>
#include <cstdint>

#define NN 500
#define GG 128
#define HH 200
#define WW 304
#define HWPX (HH * WW)            // 60800
#define WORDS 1900                // HWPX/32 exact
#define WSTRIDE 1920              // padded bit-row stride (u32), 16B multiple
#define MAXPAIRS (NN * (NN - 1) / 2)
#define MASK_THR 0.005f
#define SIGMA 2.0f

#define NCHUNK 16                 // chunks per grid row
#define CHUNKW 120                // words per chunk (last chunk: 100)

#define POPC_BLOCKS 304
#define CELLS_PER_CTA ((NN * NN + POPC_BLOCKS - 1) / POPC_BLOCKS)   // 823
#define LMAX 832

// ---- device scratch (zero-init at load; decayfinal resets per replay) ----
__device__ __align__(16) unsigned int g_bits[NN * WSTRIDE];
__device__ float g_areaf[NN];               // exact small-int float sums: order-invariant
__device__ float g_part[NN * NCHUNK];       // per-(mask,chunk) soft sums, single writer
__device__ float g_comp[NN];                // comp_iou (0 at entry)
__device__ int   g_npairs;                  // 0 at entry
__device__ unsigned int g_pair_ij[MAXPAIRS];
__device__ float g_pair_d[MAXPAIRS];

// ============================================================
// Kernel 1: x-row-stationary decode, warp-per-mask (no per-mask
// block syncs). CTA = (x-row, chunk): x chunk in smem once; warp w
// handles group members w, w+8, ... each streaming its y chunk from
// L2. Bits packed in ballot order (fixed pixel permutation:
// invariant for AND/popc/area/sums).
// ============================================================
__global__ __launch_bounds__(256) void decode_kernel(
    const float* __restrict__ segx,
    const float* __restrict__ segy,
    const int* __restrict__ x_inds,
    const int* __restrict__ y_inds)
{
    __shared__ float sxc[CHUNKW * 32];      // 15360 B
    __shared__ int   s_list[NN];
    __shared__ int   s_cnt;

    const int row  = blockIdx.x >> 4;
    const int c    = blockIdx.x & 15;
    const int tid  = threadIdx.x;
    const int warp = tid >> 5;
    const int lane = tid & 31;

    const int w0     = c * CHUNKW;
    const int nquads = (c == NCHUNK - 1) ? 25 : 30;   // quads of 128 px
    const int npx4   = nquads * 32;                   // float4 per chunk

    if (tid == 0) s_cnt = 0;
    __syncthreads();

    // build the group: masks whose x row is ours
    for (int k = tid; k < NN; k += 256)
        if (x_inds[k] == row) {
            int p = atomicAdd(&s_cnt, 1);
            s_list[p] = k;
        }
    __syncthreads();
    const int cnt = s_cnt;
    if (cnt == 0) return;

    // load x chunk into smem (coalesced float4)
    const float4* __restrict__ rx4 =
        reinterpret_cast<const float4*>(segx + (size_t)row * HWPX) + w0 * 8;
    for (int i = tid; i < npx4; i += 256)
        reinterpret_cast<float4*>(sxc)[i] = rx4[i];
    __syncthreads();

    // warp-per-mask: no further block syncs
    for (int g = warp; g < cnt; g += 8) {
        const int m  = s_list[g];
        const int yi = y_inds[m];
        const float4* __restrict__ ry4 =
            reinterpret_cast<const float4*>(segy + (size_t)yi * HWPX) + w0 * 8;
        uint4* pw = reinterpret_cast<uint4*>(g_bits + m * WSTRIDE + w0);

        float ssum  = 0.0f;
        float areaf = 0.0f;

        for (int k = 0; k < nquads; k++) {
            const float4 a = reinterpret_cast<const float4*>(sxc)[k * 32 + lane];
            const float4 b = ry4[k * 32 + lane];
            const float s0 = a.x * b.x;
            const float s1 = a.y * b.y;
            const float s2 = a.z * b.z;
            const float s3 = a.w * b.w;
            const bool p0 = s0 > MASK_THR;
            const bool p1 = s1 > MASK_THR;
            const bool p2 = s2 > MASK_THR;
            const bool p3 = s3 > MASK_THR;
            const unsigned b0 = __ballot_sync(0xffffffffu, p0);
            const unsigned b1 = __ballot_sync(0xffffffffu, p1);
            const unsigned b2 = __ballot_sync(0xffffffffu, p2);
            const unsigned b3 = __ballot_sync(0xffffffffu, p3);
            if (p0) { ssum += s0; areaf += 1.0f; }
            if (p1) { ssum += s1; areaf += 1.0f; }
            if (p2) { ssum += s2; areaf += 1.0f; }
            if (p3) { ssum += s3; areaf += 1.0f; }
            if (lane == 0)
                pw[k] = make_uint4(b0, b1, b2, b3);
        }

        // warp reduction; single writer per (mask,chunk) -> deterministic
#pragma unroll
        for (int off = 16; off > 0; off >>= 1) {
            ssum  += __shfl_down_sync(0xffffffffu, ssum,  off);
            areaf += __shfl_down_sync(0xffffffffu, areaf, off);
        }
        if (lane == 0) {
            g_part[m * NCHUNK + c] = ssum;
            atomicAdd(&g_areaf[m], areaf);   // exact int-valued float: order-invariant
        }
        // last chunk zeroes this mask's pad words [1900,1920)
        if (c == NCHUNK - 1 && lane < WSTRIDE - WORDS)
            g_bits[m * WSTRIDE + WORDS + lane] = 0u;
    }
}

// ============================================================
// Kernel 2: popc with CTA-local pair building (R9 form, proven ~5us).
// ============================================================
__global__ __launch_bounds__(256) void popc_kernel(const int* __restrict__ labels)
{
    __shared__ int s_lab[NN];
    __shared__ unsigned s_pairs[LMAX];
    __shared__ int s_cnt;
    const int tid  = threadIdx.x;
    const int lane = tid & 31;
    const int warp = tid >> 5;

    if (tid == 0) s_cnt = 0;
    for (int k = tid; k < NN; k += 256) s_lab[k] = labels[k];
    __syncthreads();

    const int lo = blockIdx.x * CELLS_PER_CTA;
    const int hi = min(lo + CELLS_PER_CTA, NN * NN);

    // phase 1: thread-granular label gate
    for (int p = lo + tid; p < hi; p += 256) {
        const int i = p / NN;
        const int j = p - i * NN;
        if (j > i && s_lab[i] == s_lab[j]) {
            int pos = atomicAdd(&s_cnt, 1);
            s_pairs[pos] = ((unsigned)i << 16) | (unsigned)j;
        }
    }
    __syncthreads();
    const int cnt = s_cnt;

    // phase 2: warp per pair
    for (int q = warp; q < cnt; q += 8) {
        const unsigned ij = s_pairs[q];
        const int i = (int)(ij >> 16);
        const int j = (int)(ij & 0xffffu);

        const uint4* __restrict__ bi = reinterpret_cast<const uint4*>(g_bits + i * WSTRIDE);
        const uint4* __restrict__ bj = reinterpret_cast<const uint4*>(g_bits + j * WSTRIDE);

        int inter = 0;
#pragma unroll 5
        for (int w = lane; w < WSTRIDE / 4; w += 32) {   // 15 iterations
            uint4 a = bi[w];
            uint4 b = bj[w];
            inter += __popc(a.x & b.x) + __popc(a.y & b.y)
                   + __popc(a.z & b.z) + __popc(a.w & b.w);
        }
#pragma unroll
        for (int off = 16; off > 0; off >>= 1)
            inter += __shfl_down_sync(0xffffffffu, inter, off);

        if (lane == 0) {
            float uni = g_areaf[i] + g_areaf[j] - (float)inter;
            float iou = (float)inter / fmaxf(uni, 1e-6f);
            atomicMax(reinterpret_cast<int*>(&g_comp[j]), __float_as_int(iou)); // iou>=0
            int pos = atomicAdd(&g_npairs, 1);
            g_pair_ij[pos] = ij;
            g_pair_d[pos] = iou;
        }
    }
}

// ============================================================
// Kernel 3 (single block, tiny data): scores + decay + output + reset.
// ============================================================
__global__ __launch_bounds__(1024) void decayfinal_kernel(
    const float* __restrict__ cate_scores,
    float* __restrict__ out)
{
    __shared__ float s_coef[NN];
    __shared__ float s_score[NN];
    const int tid = threadIdx.x;

    // phase 1: fixed-order reduce of chunk partials per mask
    for (int n = tid; n < NN; n += 1024) {
        float acc = 0.0f;
#pragma unroll
        for (int k = 0; k < NCHUNK; k++) acc += g_part[n * NCHUNK + k];
        s_score[n] = cate_scores[n] * (acc / fmaxf(g_areaf[n], 1.0f));
        s_coef[n] = 1.0f;
    }
    __syncthreads();

    // phase 2: decay terms -> order-independent min into smem coef
    const int np = g_npairs;
    for (int p = tid; p < np; p += 1024) {
        const unsigned ij = g_pair_ij[p];
        const int i = (int)(ij >> 16);
        const int j = (int)(ij & 0xffffu);
        const float d = g_pair_d[p];
        const float c = g_comp[i];
        const float term = __expf(SIGMA * (c * c - d * d));   // > 0
        atomicMin(reinterpret_cast<int*>(&s_coef[j]), __float_as_int(term));
    }
    __syncthreads();

    // phase 3: output + reset accumulators for next replay
    for (int n = tid; n < NN; n += 1024) {
        out[n] = s_score[n] * fminf(s_coef[n], 1.0f);
        g_areaf[n] = 0.0f;
        g_comp[n] = 0.0f;
    }
    if (tid == 0) g_npairs = 0;
}

extern "C" void kernel_launch(void* const* d_in, const int* in_sizes, int n_in,
                              void* d_out, int out_size)
{
    const float* cate_scores = (const float*)d_in[0];
    const float* segx        = (const float*)d_in[1];
    const float* segy        = (const float*)d_in[2];
    const int*   labels      = (const int*)d_in[3];
    const int*   x_inds      = (const int*)d_in[4];
    const int*   y_inds      = (const int*)d_in[5];
    float* out = (float*)d_out;

    decode_kernel<<<GG * NCHUNK, 256>>>(segx, segy, x_inds, y_inds);
    popc_kernel<<<POPC_BLOCKS, 256>>>(labels);
    decayfinal_kernel<<<1, 1024>>>(cate_scores, out);
}

// round 11
// speedup vs baseline: 1.0491x; 1.0491x over previous
#include <cuda_runtime.h>
#include <cstdint>

#define NN 500
#define GG 128
#define HH 200
#define WW 304
#define HWPX (HH * WW)            // 60800
#define WORDS 1900                // HWPX/32 exact
#define WSTRIDE 1920              // padded bit-row stride (u32), 16B multiple
#define MAXPAIRS (NN * (NN - 1) / 2)
#define MASK_THR 0.005f
#define SIGMA 2.0f

#define NCHUNK 8                  // chunks per mask row
#define CHUNKW 240                // words per chunk (last: 220)

#define POPC_BLOCKS 304
#define CELLS_PER_CTA ((NN * NN + POPC_BLOCKS - 1) / POPC_BLOCKS)   // 823
#define LMAX 832

// ---- device scratch (zero-init at load; popc final phase resets per replay) ----
__device__ __align__(16) unsigned int g_bits[NN * WSTRIDE];
__device__ float g_areaf[NN];             // exact small-int float sums: order-invariant
__device__ float g_part8[NN * NCHUNK];    // per-(mask,chunk) soft sums, single writer
__device__ float g_comp[NN];              // comp_iou (0 at entry)
__device__ int   g_npairs;                // 0 at entry
__device__ unsigned int g_done;           // last-CTA counter (0 at entry)
__device__ unsigned int g_pair_ij[MAXPAIRS];
__device__ float g_pair_d[MAXPAIRS];
__device__ int4  g_work[NN];              // workitems: <=4 masks sharing one x row
__device__ int   g_nwork;                 // overwritten each replay by group_kernel

// ============================================================
// Kernel 0 (1 CTA): group masks by x_ind into workitems of <=4.
// Within-row order is nondeterministic (atomicAdd) but harmless:
// all downstream per-mask outputs are single-writer / order-invariant.
// ============================================================
__global__ __launch_bounds__(512) void group_kernel(const int* __restrict__ x_inds)
{
    __shared__ int s_cnt[GG], s_off[GG], s_fill[GG], s_wio[GG];
    __shared__ int s_sorted[NN];
    const int tid = threadIdx.x;

    if (tid < GG) { s_cnt[tid] = 0; s_fill[tid] = 0; }
    __syncthreads();
    if (tid < NN) atomicAdd(&s_cnt[x_inds[tid]], 1);
    __syncthreads();
    if (tid == 0) {
        int acc = 0, wacc = 0;
        for (int r = 0; r < GG; r++) {
            s_off[r] = acc;  acc  += s_cnt[r];
            s_wio[r] = wacc; wacc += (s_cnt[r] + 3) >> 2;
        }
        g_nwork = wacc;
    }
    __syncthreads();
    if (tid < NN) {
        const int r = x_inds[tid];
        const int p = atomicAdd(&s_fill[r], 1);
        s_sorted[s_off[r] + p] = tid;
    }
    __syncthreads();
    if (tid < GG) {
        const int c = s_cnt[tid], o = s_off[tid], w = s_wio[tid];
        for (int g = 0; g * 4 < c; g++) {
            int4 it;
            it.x = s_sorted[o + g * 4];
            it.y = (g * 4 + 1 < c) ? s_sorted[o + g * 4 + 1] : -1;
            it.z = (g * 4 + 2 < c) ? s_sorted[o + g * 4 + 2] : -1;
            it.w = (g * 4 + 3 < c) ? s_sorted[o + g * 4 + 3] : -1;
            g_work[w + g] = it;
        }
    }
}

// per-slot quad processing (warp-synchronous; branch is CTA-uniform)
#define SLOT(PB, PW, SS, AR) do {                                        \
    const float4 b = *(PB);                                              \
    const float s0 = a.x * b.x, s1 = a.y * b.y;                          \
    const float s2 = a.z * b.z, s3 = a.w * b.w;                          \
    const bool p0 = s0 > MASK_THR, p1 = s1 > MASK_THR;                   \
    const bool p2 = s2 > MASK_THR, p3 = s3 > MASK_THR;                   \
    const unsigned c0 = __ballot_sync(0xffffffffu, p0);                  \
    const unsigned c1 = __ballot_sync(0xffffffffu, p1);                  \
    const unsigned c2 = __ballot_sync(0xffffffffu, p2);                  \
    const unsigned c3 = __ballot_sync(0xffffffffu, p3);                  \
    if (p0) { SS += s0; AR += 1.0f; }                                    \
    if (p1) { SS += s1; AR += 1.0f; }                                    \
    if (p2) { SS += s2; AR += 1.0f; }                                    \
    if (p3) { SS += s3; AR += 1.0f; }                                    \
    if (lane == 0) *(PW) = make_uint4(c0, c1, c2, c3);                   \
} while (0)

// ============================================================
// Kernel 1: decode, R7 parallelism (8 warps cooperate per chunk)
// with x-amortization: one x load feeds up to 4 masks' y streams.
// blockIdx.x = workitem*8 + chunk; wi >= g_nwork exits.
// ============================================================
__global__ __launch_bounds__(256) void decode_kernel(
    const float* __restrict__ segx,
    const float* __restrict__ segy,
    const int* __restrict__ x_inds,
    const int* __restrict__ y_inds)
{
    const int wi = blockIdx.x >> 3;
    if (wi >= g_nwork) return;
    const int c    = blockIdx.x & 7;
    const int tid  = threadIdx.x;
    const int warp = tid >> 5;
    const int lane = tid & 31;

    const int4 it = g_work[wi];
    const int m0 = it.x, m1 = it.y, m2 = it.z, m3 = it.w;

    const int w0 = c * CHUNKW;
    const int nquads = ((c == NCHUNK - 1) ? (WORDS - w0) : CHUNKW) >> 2;  // 60 or 55
    const size_t f4base = (size_t)w0 * 8 + warp * 32 + lane;

    const float4* pa = reinterpret_cast<const float4*>(segx + (size_t)x_inds[m0] * HWPX) + f4base;
    const float4* pb0 = reinterpret_cast<const float4*>(segy + (size_t)y_inds[m0] * HWPX) + f4base;
    const float4* pb1 = (m1 >= 0) ? reinterpret_cast<const float4*>(segy + (size_t)y_inds[m1] * HWPX) + f4base : pb0;
    const float4* pb2 = (m2 >= 0) ? reinterpret_cast<const float4*>(segy + (size_t)y_inds[m2] * HWPX) + f4base : pb0;
    const float4* pb3 = (m3 >= 0) ? reinterpret_cast<const float4*>(segy + (size_t)y_inds[m3] * HWPX) + f4base : pb0;
    uint4* pw0 = reinterpret_cast<uint4*>(g_bits + m0 * WSTRIDE + w0) + warp;
    uint4* pw1 = (m1 >= 0) ? reinterpret_cast<uint4*>(g_bits + m1 * WSTRIDE + w0) + warp : pw0;
    uint4* pw2 = (m2 >= 0) ? reinterpret_cast<uint4*>(g_bits + m2 * WSTRIDE + w0) + warp : pw0;
    uint4* pw3 = (m3 >= 0) ? reinterpret_cast<uint4*>(g_bits + m3 * WSTRIDE + w0) + warp : pw0;

    float ss0 = 0.f, ss1 = 0.f, ss2 = 0.f, ss3 = 0.f;
    float ar0 = 0.f, ar1 = 0.f, ar2 = 0.f, ar3 = 0.f;

    for (int k = warp; k < nquads; k += 8) {
        const float4 a = *pa;  pa += 256;
        SLOT(pb0, pw0, ss0, ar0);             pb0 += 256; pw0 += 8;
        if (m1 >= 0) { SLOT(pb1, pw1, ss1, ar1); pb1 += 256; pw1 += 8; }
        if (m2 >= 0) { SLOT(pb2, pw2, ss2, ar2); pb2 += 256; pw2 += 8; }
        if (m3 >= 0) { SLOT(pb3, pw3, ss3, ar3); pb3 += 256; pw3 += 8; }
    }

    // warp reduce all slot accumulators
#pragma unroll
    for (int off = 16; off > 0; off >>= 1) {
        ss0 += __shfl_down_sync(0xffffffffu, ss0, off);
        ss1 += __shfl_down_sync(0xffffffffu, ss1, off);
        ss2 += __shfl_down_sync(0xffffffffu, ss2, off);
        ss3 += __shfl_down_sync(0xffffffffu, ss3, off);
        ar0 += __shfl_down_sync(0xffffffffu, ar0, off);
        ar1 += __shfl_down_sync(0xffffffffu, ar1, off);
        ar2 += __shfl_down_sync(0xffffffffu, ar2, off);
        ar3 += __shfl_down_sync(0xffffffffu, ar3, off);
    }
    __shared__ float s_s[8][4];
    __shared__ float s_a[8][4];
    if (lane == 0) {
        s_s[warp][0] = ss0; s_s[warp][1] = ss1; s_s[warp][2] = ss2; s_s[warp][3] = ss3;
        s_a[warp][0] = ar0; s_a[warp][1] = ar1; s_a[warp][2] = ar2; s_a[warp][3] = ar3;
    }
    __syncthreads();
    if (tid < 4) {
        const int m = (tid == 0) ? m0 : (tid == 1) ? m1 : (tid == 2) ? m2 : m3;
        if (m >= 0) {
            float ts = 0.f, ta = 0.f;
#pragma unroll
            for (int w = 0; w < 8; w++) { ts += s_s[w][tid]; ta += s_a[w][tid]; }
            g_part8[m * NCHUNK + c] = ts;     // single writer: deterministic
            atomicAdd(&g_areaf[m], ta);       // exact int-valued float: order-invariant
        }
    }
    // last chunk zeroes pad words [1900,1920) for each valid mask
    if (c == NCHUNK - 1 && tid < (WSTRIDE - WORDS) * 4) {
        const int slot = tid / (WSTRIDE - WORDS);
        const int o    = tid % (WSTRIDE - WORDS);
        const int m = (slot == 0) ? m0 : (slot == 1) ? m1 : (slot == 2) ? m2 : m3;
        if (m >= 0) g_bits[m * WSTRIDE + WORDS + o] = 0u;
    }
}

// ============================================================
// Kernel 2: popc (R9 CTA-local pair building) + last-CTA final phase.
// ============================================================
__global__ __launch_bounds__(256) void popc_kernel(
    const int* __restrict__ labels,
    const float* __restrict__ cate_scores,
    float* __restrict__ out)
{
    __shared__ int s_lab[NN];
    __shared__ unsigned s_pairs[LMAX];
    __shared__ int s_cnt;
    __shared__ unsigned s_last;
    const int tid  = threadIdx.x;
    const int lane = tid & 31;
    const int warp = tid >> 5;

    if (tid == 0) s_cnt = 0;
    for (int k = tid; k < NN; k += 256) s_lab[k] = labels[k];
    __syncthreads();

    const int lo = blockIdx.x * CELLS_PER_CTA;
    const int hi = min(lo + CELLS_PER_CTA, NN * NN);

    // phase 1: thread-granular label gate
    for (int p = lo + tid; p < hi; p += 256) {
        const int i = p / NN;
        const int j = p - i * NN;
        if (j > i && s_lab[i] == s_lab[j]) {
            int pos = atomicAdd(&s_cnt, 1);
            s_pairs[pos] = ((unsigned)i << 16) | (unsigned)j;
        }
    }
    __syncthreads();
    const int cnt = s_cnt;

    // phase 2: warp per pair
    for (int q = warp; q < cnt; q += 8) {
        const unsigned ij = s_pairs[q];
        const int i = (int)(ij >> 16);
        const int j = (int)(ij & 0xffffu);

        const uint4* __restrict__ bi = reinterpret_cast<const uint4*>(g_bits + i * WSTRIDE);
        const uint4* __restrict__ bj = reinterpret_cast<const uint4*>(g_bits + j * WSTRIDE);

        int inter = 0;
#pragma unroll 5
        for (int w = lane; w < WSTRIDE / 4; w += 32) {
            uint4 a = bi[w];
            uint4 b = bj[w];
            inter += __popc(a.x & b.x) + __popc(a.y & b.y)
                   + __popc(a.z & b.z) + __popc(a.w & b.w);
        }
#pragma unroll
        for (int off = 16; off > 0; off >>= 1)
            inter += __shfl_down_sync(0xffffffffu, inter, off);

        if (lane == 0) {
            float uni = g_areaf[i] + g_areaf[j] - (float)inter;
            float iou = (float)inter / fmaxf(uni, 1e-6f);
            atomicMax(reinterpret_cast<int*>(&g_comp[j]), __float_as_int(iou)); // iou>=0
            int pos = atomicAdd(&g_npairs, 1);
            g_pair_ij[pos] = ij;
            g_pair_d[pos] = iou;
        }
    }

    // ---- last CTA runs the final phase (order-independent reductions) ----
    __threadfence();
    if (tid == 0)
        s_last = (atomicAdd(&g_done, 1u) == (unsigned)gridDim.x - 1u);
    __syncthreads();
    if (!s_last) return;

    __shared__ float s_coef[NN];
    __shared__ float s_score[NN];

    for (int n = tid; n < NN; n += 256) {
        float acc = 0.0f;
#pragma unroll
        for (int k = 0; k < NCHUNK; k++) acc += g_part8[n * NCHUNK + k];
        s_score[n] = cate_scores[n] * (acc / fmaxf(g_areaf[n], 1.0f));
        s_coef[n] = 1.0f;
    }
    __syncthreads();

    const int np = g_npairs;
    for (int p = tid; p < np; p += 256) {
        const unsigned ij = g_pair_ij[p];
        const int i = (int)(ij >> 16);
        const int j = (int)(ij & 0xffffu);
        const float d = g_pair_d[p];
        const float cc = g_comp[i];
        const float term = __expf(SIGMA * (cc * cc - d * d));   // > 0
        atomicMin(reinterpret_cast<int*>(&s_coef[j]), __float_as_int(term));
    }
    __syncthreads();

    for (int n = tid; n < NN; n += 256) {
        out[n] = s_score[n] * fminf(s_coef[n], 1.0f);
        g_areaf[n] = 0.0f;
        g_comp[n] = 0.0f;
    }
    if (tid == 0) { g_npairs = 0; g_done = 0u; }
}

extern "C" void kernel_launch(void* const* d_in, const int* in_sizes, int n_in,
                              void* d_out, int out_size)
{
    const float* cate_scores = (const float*)d_in[0];
    const float* segx        = (const float*)d_in[1];
    const float* segy        = (const float*)d_in[2];
    const int*   labels      = (const int*)d_in[3];
    const int*   x_inds      = (const int*)d_in[4];
    const int*   y_inds      = (const int*)d_in[5];
    float* out = (float*)d_out;

    group_kernel<<<1, 512>>>(x_inds);
    decode_kernel<<<NN * NCHUNK, 256>>>(segx, segy, x_inds, y_inds);
    popc_kernel<<<POPC_BLOCKS, 256>>>(labels, cate_scores, out);
}

// round 12
// speedup vs baseline: 1.2313x; 1.1737x over previous
#include <cuda_runtime.h>
#include <cstdint>

#define NN 500
#define GG 128
#define HH 200
#define WW 304
#define HWPX (HH * WW)            // 60800
#define WORDS 1900                // HWPX/32 exact
#define WSTRIDE 1920              // padded bit-row stride (u32), 16B multiple
#define MAXPAIRS (NN * (NN - 1) / 2)
#define MASK_THR 0.005f
#define SIGMA 2.0f

#define NCHUNK 8                  // chunks per mask
#define CHUNKW 240                // words per chunk (last: 220). multiple of 4.

#define POPC_BLOCKS 304
#define CELLS_PER_CTA ((NN * NN + POPC_BLOCKS - 1) / POPC_BLOCKS)   // 823
#define LMAX 832

// ---- device scratch (zero-init at load; popc final phase resets per replay) ----
__device__ __align__(16) unsigned int g_bits[NN * WSTRIDE];
__device__ float g_areaf[NN];             // exact small-int float sums: order-invariant
__device__ float g_part8[NN * NCHUNK];    // per-(mask,chunk) soft sums, single writer
__device__ float g_comp[NN];              // comp_iou (0 at entry)
__device__ int   g_npairs;                // 0 at entry
__device__ unsigned int g_done;           // last-CTA counter (0 at entry)
__device__ unsigned int g_pair_ij[MAXPAIRS];
__device__ float g_pair_d[MAXPAIRS];

// ============================================================
// Kernel 1: decode (R7 form, proven 23.6us = LTS-cap bound).
// Warp iteration = 128 consecutive pixels (lane L loads float4 #L).
// Bits packed in ballot order (fixed pixel permutation: invariant
// for AND/popc/area/sums). blockIdx.x = mask*8 + chunk.
// ============================================================
__global__ __launch_bounds__(256) void decode_kernel(
    const float* __restrict__ segx,
    const float* __restrict__ segy,
    const int* __restrict__ x_inds,
    const int* __restrict__ y_inds)
{
    const int n    = blockIdx.x >> 3;
    const int c    = blockIdx.x & 7;
    const int tid  = threadIdx.x;
    const int warp = tid >> 5;
    const int lane = tid & 31;

    const int xi = x_inds[n];
    const int yi = y_inds[n];
    const float4* __restrict__ rx = reinterpret_cast<const float4*>(segx + (size_t)xi * HWPX);
    const float4* __restrict__ ry = reinterpret_cast<const float4*>(segy + (size_t)yi * HWPX);

    const int w0 = c * CHUNKW;
    const int nquads = ((c == NCHUNK - 1) ? (WORDS - w0) : CHUNKW) >> 2;   // 60 or 55

    float ssum  = 0.0f;
    float areaf = 0.0f;

    const float4* pa = rx + (size_t)w0 * 8 + warp * 32 + lane;
    const float4* pb = ry + (size_t)w0 * 8 + warp * 32 + lane;
    uint4* pw = reinterpret_cast<uint4*>(g_bits + n * WSTRIDE + w0) + warp;

    for (int k = warp; k < nquads; k += 8, pa += 256, pb += 256, pw += 8) {
        const float4 a = *pa;
        const float4 b = *pb;
        const float s0 = a.x * b.x;
        const float s1 = a.y * b.y;
        const float s2 = a.z * b.z;
        const float s3 = a.w * b.w;
        const bool p0 = s0 > MASK_THR;
        const bool p1 = s1 > MASK_THR;
        const bool p2 = s2 > MASK_THR;
        const bool p3 = s3 > MASK_THR;
        const unsigned b0 = __ballot_sync(0xffffffffu, p0);
        const unsigned b1 = __ballot_sync(0xffffffffu, p1);
        const unsigned b2 = __ballot_sync(0xffffffffu, p2);
        const unsigned b3 = __ballot_sync(0xffffffffu, p3);
        if (p0) { ssum += s0; areaf += 1.0f; }
        if (p1) { ssum += s1; areaf += 1.0f; }
        if (p2) { ssum += s2; areaf += 1.0f; }
        if (p3) { ssum += s3; areaf += 1.0f; }
        if (lane == 0)
            *pw = make_uint4(b0, b1, b2, b3);
    }
    // last chunk zeroes the pad words [1900,1920)
    if (c == NCHUNK - 1 && tid < WSTRIDE - WORDS)
        g_bits[n * WSTRIDE + WORDS + tid] = 0u;

    // block reduction (8 warps, two floats)
    __shared__ float s_sum[8];
    __shared__ float s_area[8];
#pragma unroll
    for (int off = 16; off > 0; off >>= 1) {
        ssum  += __shfl_down_sync(0xffffffffu, ssum,  off);
        areaf += __shfl_down_sync(0xffffffffu, areaf, off);
    }
    if (lane == 0) { s_sum[warp] = ssum; s_area[warp] = areaf; }
    __syncthreads();
    if (tid == 0) {
        float tsum = 0.0f, tarea = 0.0f;
#pragma unroll
        for (int k = 0; k < 8; k++) { tsum += s_sum[k]; tarea += s_area[k]; }
        g_part8[n * NCHUNK + c] = tsum;      // single writer: deterministic
        atomicAdd(&g_areaf[n], tarea);       // exact int-valued float: order-invariant
    }
}

// ============================================================
// Kernel 2: popc (R9 CTA-local pair building, proven ~5us)
// + last-CTA final phase (order-independent reductions).
// ============================================================
__global__ __launch_bounds__(256) void popc_kernel(
    const int* __restrict__ labels,
    const float* __restrict__ cate_scores,
    float* __restrict__ out)
{
    __shared__ int s_lab[NN];
    __shared__ unsigned s_pairs[LMAX];
    __shared__ int s_cnt;
    __shared__ unsigned s_last;
    const int tid  = threadIdx.x;
    const int lane = tid & 31;
    const int warp = tid >> 5;

    if (tid == 0) s_cnt = 0;
    for (int k = tid; k < NN; k += 256) s_lab[k] = labels[k];
    __syncthreads();

    const int lo = blockIdx.x * CELLS_PER_CTA;
    const int hi = min(lo + CELLS_PER_CTA, NN * NN);

    // phase 1: thread-granular label gate
    for (int p = lo + tid; p < hi; p += 256) {
        const int i = p / NN;
        const int j = p - i * NN;
        if (j > i && s_lab[i] == s_lab[j]) {
            int pos = atomicAdd(&s_cnt, 1);
            s_pairs[pos] = ((unsigned)i << 16) | (unsigned)j;
        }
    }
    __syncthreads();
    const int cnt = s_cnt;

    // phase 2: warp per pair
    for (int q = warp; q < cnt; q += 8) {
        const unsigned ij = s_pairs[q];
        const int i = (int)(ij >> 16);
        const int j = (int)(ij & 0xffffu);

        const uint4* __restrict__ bi = reinterpret_cast<const uint4*>(g_bits + i * WSTRIDE);
        const uint4* __restrict__ bj = reinterpret_cast<const uint4*>(g_bits + j * WSTRIDE);

        int inter = 0;
#pragma unroll 5
        for (int w = lane; w < WSTRIDE / 4; w += 32) {   // 15 iterations
            uint4 a = bi[w];
            uint4 b = bj[w];
            inter += __popc(a.x & b.x) + __popc(a.y & b.y)
                   + __popc(a.z & b.z) + __popc(a.w & b.w);
        }
#pragma unroll
        for (int off = 16; off > 0; off >>= 1)
            inter += __shfl_down_sync(0xffffffffu, inter, off);

        if (lane == 0) {
            float uni = g_areaf[i] + g_areaf[j] - (float)inter;
            float iou = (float)inter / fmaxf(uni, 1e-6f);
            atomicMax(reinterpret_cast<int*>(&g_comp[j]), __float_as_int(iou)); // iou>=0
            int pos = atomicAdd(&g_npairs, 1);
            g_pair_ij[pos] = ij;
            g_pair_d[pos] = iou;
        }
    }

    // ---- last CTA runs the final phase (all reductions order-independent) ----
    __threadfence();
    if (tid == 0)
        s_last = (atomicAdd(&g_done, 1u) == (unsigned)gridDim.x - 1u);
    __syncthreads();
    if (!s_last) return;

    __shared__ float s_coef[NN];
    __shared__ float s_score[NN];

    // scores: fixed-order reduce of 8 chunk partials per mask
    for (int n = tid; n < NN; n += 256) {
        float acc = 0.0f;
#pragma unroll
        for (int k = 0; k < NCHUNK; k++) acc += g_part8[n * NCHUNK + k];
        s_score[n] = cate_scores[n] * (acc / fmaxf(g_areaf[n], 1.0f));
        s_coef[n] = 1.0f;
    }
    __syncthreads();

    // decay terms -> order-independent min into smem coef
    const int np = g_npairs;
    for (int p = tid; p < np; p += 256) {
        const unsigned ij = g_pair_ij[p];
        const int i = (int)(ij >> 16);
        const int j = (int)(ij & 0xffffu);
        const float d = g_pair_d[p];
        const float cc = g_comp[i];
        const float term = __expf(SIGMA * (cc * cc - d * d));   // > 0
        atomicMin(reinterpret_cast<int*>(&s_coef[j]), __float_as_int(term));
    }
    __syncthreads();

    // output + reset accumulators for next replay
    for (int n = tid; n < NN; n += 256) {
        out[n] = s_score[n] * fminf(s_coef[n], 1.0f);
        g_areaf[n] = 0.0f;
        g_comp[n] = 0.0f;
    }
    if (tid == 0) { g_npairs = 0; g_done = 0u; }
}

extern "C" void kernel_launch(void* const* d_in, const int* in_sizes, int n_in,
                              void* d_out, int out_size)
{
    const float* cate_scores = (const float*)d_in[0];
    const float* segx        = (const float*)d_in[1];
    const float* segy        = (const float*)d_in[2];
    const int*   labels      = (const int*)d_in[3];
    const int*   x_inds      = (const int*)d_in[4];
    const int*   y_inds      = (const int*)d_in[5];
    float* out = (float*)d_out;

    decode_kernel<<<NN * NCHUNK, 256>>>(segx, segy, x_inds, y_inds);
    popc_kernel<<<POPC_BLOCKS, 256>>>(labels, cate_scores, out);
}

// round 13
// speedup vs baseline: 1.3320x; 1.0818x over previous
#include <cuda_runtime.h>
#include <cstdint>

#define NN 500
#define GG 128
#define HH 200
#define WW 304
#define HWPX (HH * WW)            // 60800
#define WORDS 1900                // HWPX/32 exact
#define WSTRIDE 1920              // padded bit-row stride (u32), 16B multiple
#define MAXPAIRS (NN * (NN - 1) / 2)
#define MASK_THR 0.005f
#define SIGMA 2.0f

#define NCHUNK 8                  // chunks per mask
#define CHUNKW 240                // words per chunk (last: 220). multiple of 4.

#define POPC_BLOCKS 608
#define CELLS_PER_CTA ((NN * NN + POPC_BLOCKS - 1) / POPC_BLOCKS)   // 412
#define LMAX 416

// ---- device scratch (zero-init at load; decayfinal resets per replay) ----
__device__ __align__(16) unsigned int g_bits[NN * WSTRIDE];
__device__ float g_areaf[NN];             // exact small-int float sums: order-invariant
__device__ float g_part8[NN * NCHUNK];    // per-(mask,chunk) soft sums, single writer
__device__ float g_comp[NN];              // comp_iou (0 at entry)
__device__ int   g_npairs;                // 0 at entry
__device__ unsigned int g_pair_ij[MAXPAIRS];
__device__ float g_pair_d[MAXPAIRS];

// process one quad (index k): ballots + predicated sums + lane-0 STG.128
#define PROC(A, B, K) do {                                               \
    const float s0 = (A).x * (B).x, s1 = (A).y * (B).y;                  \
    const float s2 = (A).z * (B).z, s3 = (A).w * (B).w;                  \
    const bool p0 = s0 > MASK_THR, p1 = s1 > MASK_THR;                   \
    const bool p2 = s2 > MASK_THR, p3 = s3 > MASK_THR;                   \
    const unsigned c0 = __ballot_sync(0xffffffffu, p0);                  \
    const unsigned c1 = __ballot_sync(0xffffffffu, p1);                  \
    const unsigned c2 = __ballot_sync(0xffffffffu, p2);                  \
    const unsigned c3 = __ballot_sync(0xffffffffu, p3);                  \
    if (p0) { ssum += s0; areaf += 1.0f; }                               \
    if (p1) { ssum += s1; areaf += 1.0f; }                               \
    if (p2) { ssum += s2; areaf += 1.0f; }                               \
    if (p3) { ssum += s3; areaf += 1.0f; }                               \
    if (lane == 0) pwB[K] = make_uint4(c0, c1, c2, c3);                  \
} while (0)

// ============================================================
// Kernel 1: decode (R7 structure, 2x unrolled for MLP).
// Warp iteration = 128 consecutive pixels (lane L loads float4 #L).
// Bits packed in ballot order (fixed pixel permutation: invariant
// for AND/popc/area/sums). blockIdx.x = mask*8 + chunk.
// ============================================================
__global__ __launch_bounds__(256) void decode_kernel(
    const float* __restrict__ segx,
    const float* __restrict__ segy,
    const int* __restrict__ x_inds,
    const int* __restrict__ y_inds)
{
    const int n    = blockIdx.x >> 3;
    const int c    = blockIdx.x & 7;
    const int tid  = threadIdx.x;
    const int warp = tid >> 5;
    const int lane = tid & 31;

    const int xi = x_inds[n];
    const int yi = y_inds[n];

    const int w0 = c * CHUNKW;
    const int nquads = ((c == NCHUNK - 1) ? (WORDS - w0) : CHUNKW) >> 2;   // 60 or 55

    // quad k: float4 index = w0*8 + 32k + lane; uint4 bits index = w0/4 + k
    const float4* __restrict__ bx =
        reinterpret_cast<const float4*>(segx + (size_t)xi * HWPX) + w0 * 8 + lane;
    const float4* __restrict__ by =
        reinterpret_cast<const float4*>(segy + (size_t)yi * HWPX) + w0 * 8 + lane;
    uint4* pwB = reinterpret_cast<uint4*>(g_bits + n * WSTRIDE + w0);

    float ssum  = 0.0f;
    float areaf = 0.0f;

    int k = warp;
    for (; k + 8 < nquads; k += 16) {
        // issue all 4 loads before consuming: 4 LDG.128 in flight per thread
        const float4 a0 = bx[32 * k];
        const float4 b0 = by[32 * k];
        const float4 a1 = bx[32 * (k + 8)];
        const float4 b1 = by[32 * (k + 8)];
        PROC(a0, b0, k);
        PROC(a1, b1, k + 8);
    }
    if (k < nquads) {
        const float4 a0 = bx[32 * k];
        const float4 b0 = by[32 * k];
        PROC(a0, b0, k);
    }

    // last chunk zeroes the pad words [1900,1920)
    if (c == NCHUNK - 1 && tid < WSTRIDE - WORDS)
        g_bits[n * WSTRIDE + WORDS + tid] = 0u;

    // block reduction (8 warps, two floats)
    __shared__ float s_sum[8];
    __shared__ float s_area[8];
#pragma unroll
    for (int off = 16; off > 0; off >>= 1) {
        ssum  += __shfl_down_sync(0xffffffffu, ssum,  off);
        areaf += __shfl_down_sync(0xffffffffu, areaf, off);
    }
    if (lane == 0) { s_sum[warp] = ssum; s_area[warp] = areaf; }
    __syncthreads();
    if (tid == 0) {
        float tsum = 0.0f, tarea = 0.0f;
#pragma unroll
        for (int q = 0; q < 8; q++) { tsum += s_sum[q]; tarea += s_area[q]; }
        g_part8[n * NCHUNK + c] = tsum;      // single writer: deterministic
        atomicAdd(&g_areaf[n], tarea);       // exact int-valued float: order-invariant
    }
}

// ============================================================
// Kernel 2: popc with CTA-local pair building (R9 form, 608 CTAs).
// ============================================================
__global__ __launch_bounds__(256) void popc_kernel(const int* __restrict__ labels)
{
    __shared__ int s_lab[NN];
    __shared__ unsigned s_pairs[LMAX];
    __shared__ int s_cnt;
    const int tid  = threadIdx.x;
    const int lane = tid & 31;
    const int warp = tid >> 5;

    if (tid == 0) s_cnt = 0;
    for (int q = tid; q < NN; q += 256) s_lab[q] = labels[q];
    __syncthreads();

    const int lo = blockIdx.x * CELLS_PER_CTA;
    const int hi = min(lo + CELLS_PER_CTA, NN * NN);

    // phase 1: thread-granular label gate (~1.6 iterations)
    for (int p = lo + tid; p < hi; p += 256) {
        const int i = p / NN;
        const int j = p - i * NN;
        if (j > i && s_lab[i] == s_lab[j]) {
            int pos = atomicAdd(&s_cnt, 1);
            s_pairs[pos] = ((unsigned)i << 16) | (unsigned)j;
        }
    }
    __syncthreads();
    const int cnt = s_cnt;

    // phase 2: warp per pair
    for (int q = warp; q < cnt; q += 8) {
        const unsigned ij = s_pairs[q];
        const int i = (int)(ij >> 16);
        const int j = (int)(ij & 0xffffu);

        const uint4* __restrict__ bi = reinterpret_cast<const uint4*>(g_bits + i * WSTRIDE);
        const uint4* __restrict__ bj = reinterpret_cast<const uint4*>(g_bits + j * WSTRIDE);

        int inter = 0;
#pragma unroll 5
        for (int w = lane; w < WSTRIDE / 4; w += 32) {   // 15 iterations
            uint4 a = bi[w];
            uint4 b = bj[w];
            inter += __popc(a.x & b.x) + __popc(a.y & b.y)
                   + __popc(a.z & b.z) + __popc(a.w & b.w);
        }
#pragma unroll
        for (int off = 16; off > 0; off >>= 1)
            inter += __shfl_down_sync(0xffffffffu, inter, off);

        if (lane == 0) {
            float uni = g_areaf[i] + g_areaf[j] - (float)inter;
            float iou = (float)inter / fmaxf(uni, 1e-6f);
            atomicMax(reinterpret_cast<int*>(&g_comp[j]), __float_as_int(iou)); // iou>=0
            int pos = atomicAdd(&g_npairs, 1);
            g_pair_ij[pos] = ij;
            g_pair_d[pos] = iou;
        }
    }
}

// ============================================================
// Kernel 3 (single block, tiny data): scores + decay + output + reset.
// ============================================================
__global__ __launch_bounds__(1024) void decayfinal_kernel(
    const float* __restrict__ cate_scores,
    float* __restrict__ out)
{
    __shared__ float s_coef[NN];
    __shared__ float s_score[NN];
    const int tid = threadIdx.x;

    // phase 1: fixed-order reduce of 8 chunk partials per mask
    for (int n = tid; n < NN; n += 1024) {
        float acc = 0.0f;
#pragma unroll
        for (int k = 0; k < NCHUNK; k++) acc += g_part8[n * NCHUNK + k];
        s_score[n] = cate_scores[n] * (acc / fmaxf(g_areaf[n], 1.0f));
        s_coef[n] = 1.0f;
    }
    __syncthreads();

    // phase 2: decay terms -> order-independent min into smem coef
    const int np = g_npairs;
    for (int p = tid; p < np; p += 1024) {
        const unsigned ij = g_pair_ij[p];
        const int i = (int)(ij >> 16);
        const int j = (int)(ij & 0xffffu);
        const float d = g_pair_d[p];
        const float c = g_comp[i];
        const float term = __expf(SIGMA * (c * c - d * d));   // > 0
        atomicMin(reinterpret_cast<int*>(&s_coef[j]), __float_as_int(term));
    }
    __syncthreads();

    // phase 3: output + reset accumulators for next replay
    for (int n = tid; n < NN; n += 1024) {
        out[n] = s_score[n] * fminf(s_coef[n], 1.0f);
        g_areaf[n] = 0.0f;
        g_comp[n] = 0.0f;
    }
    if (tid == 0) g_npairs = 0;
}

extern "C" void kernel_launch(void* const* d_in, const int* in_sizes, int n_in,
                              void* d_out, int out_size)
{
    const float* cate_scores = (const float*)d_in[0];
    const float* segx        = (const float*)d_in[1];
    const float* segy        = (const float*)d_in[2];
    const int*   labels      = (const int*)d_in[3];
    const int*   x_inds      = (const int*)d_in[4];
    const int*   y_inds      = (const int*)d_in[5];
    float* out = (float*)d_out;

    decode_kernel<<<NN * NCHUNK, 256>>>(segx, segy, x_inds, y_inds);
    popc_kernel<<<POPC_BLOCKS, 256>>>(labels);
    decayfinal_kernel<<<1, 1024>>>(cate_scores, out);
}

// round 14
// speedup vs baseline: 1.3902x; 1.0437x over previous
#include <cuda_runtime.h>
#include <cstdint>

#define NN 500
#define GG 128
#define HH 200
#define WW 304
#define HWPX (HH * WW)            // 60800
#define WORDS 1900                // HWPX/32 exact
#define WSTRIDE 1920              // padded bit-row stride (u32), 16B multiple
#define MAXPAIRS (NN * (NN - 1) / 2)
#define MASK_THR 0.005f
#define SIGMA 2.0f

#define NCHUNK 12                 // chunks per mask: grid 6000 = 4.93 waves of 1216
#define CHUNKW 160                // words per chunk (last chunk: 140). multiple of 4.

#define POPC_BLOCKS 1216
#define CELLS_PER_CTA ((NN * NN + POPC_BLOCKS - 1) / POPC_BLOCKS)   // 206
#define LMAX 224

// ---- device scratch (zero-init at load; decayfinal resets per replay) ----
__device__ __align__(16) unsigned int g_bits[NN * WSTRIDE];
__device__ float g_areaf[NN];             // exact small-int float sums: order-invariant
__device__ float g_part[NN * NCHUNK];     // per-(mask,chunk) soft sums, single writer
__device__ float g_comp[NN];              // comp_iou (0 at entry)
__device__ int   g_npairs;                // 0 at entry
__device__ unsigned int g_pair_ij[MAXPAIRS];
__device__ float g_pair_d[MAXPAIRS];

// process one quad (index k): ballots + predicated sums + lane-0 STG.128
#define PROC(A, B, K) do {                                               \
    const float s0 = (A).x * (B).x, s1 = (A).y * (B).y;                  \
    const float s2 = (A).z * (B).z, s3 = (A).w * (B).w;                  \
    const bool p0 = s0 > MASK_THR, p1 = s1 > MASK_THR;                   \
    const bool p2 = s2 > MASK_THR, p3 = s3 > MASK_THR;                   \
    const unsigned c0 = __ballot_sync(0xffffffffu, p0);                  \
    const unsigned c1 = __ballot_sync(0xffffffffu, p1);                  \
    const unsigned c2 = __ballot_sync(0xffffffffu, p2);                  \
    const unsigned c3 = __ballot_sync(0xffffffffu, p3);                  \
    if (p0) { ssum += s0; areaf += 1.0f; }                               \
    if (p1) { ssum += s1; areaf += 1.0f; }                               \
    if (p2) { ssum += s2; areaf += 1.0f; }                               \
    if (p3) { ssum += s3; areaf += 1.0f; }                               \
    if (lane == 0) pwB[K] = make_uint4(c0, c1, c2, c3);                  \
} while (0)

// ============================================================
// Kernel 1: decode (R13 structure, 2x unroll, 12 chunks/mask).
// Warp iteration = 128 consecutive pixels (lane L loads float4 #L).
// Bits packed in ballot order (fixed pixel permutation: invariant
// for AND/popc/area/sums). blockIdx.x = mask*12 + chunk.
// ============================================================
__global__ __launch_bounds__(256) void decode_kernel(
    const float* __restrict__ segx,
    const float* __restrict__ segy,
    const int* __restrict__ x_inds,
    const int* __restrict__ y_inds)
{
    const int n    = blockIdx.x / NCHUNK;
    const int c    = blockIdx.x - n * NCHUNK;
    const int tid  = threadIdx.x;
    const int warp = tid >> 5;
    const int lane = tid & 31;

    const int xi = x_inds[n];
    const int yi = y_inds[n];

    const int w0 = c * CHUNKW;
    const int nquads = ((c == NCHUNK - 1) ? (WORDS - w0) : CHUNKW) >> 2;   // 40 or 35

    // quad k: float4 index = w0*8 + 32k + lane; uint4 bits index = w0/4 + k
    const float4* __restrict__ bx =
        reinterpret_cast<const float4*>(segx + (size_t)xi * HWPX) + w0 * 8 + lane;
    const float4* __restrict__ by =
        reinterpret_cast<const float4*>(segy + (size_t)yi * HWPX) + w0 * 8 + lane;
    uint4* pwB = reinterpret_cast<uint4*>(g_bits + n * WSTRIDE + w0);

    float ssum  = 0.0f;
    float areaf = 0.0f;

    int k = warp;
    for (; k + 8 < nquads; k += 16) {
        // 4 LDG.128 in flight per thread before first consume
        const float4 a0 = bx[32 * k];
        const float4 b0 = by[32 * k];
        const float4 a1 = bx[32 * (k + 8)];
        const float4 b1 = by[32 * (k + 8)];
        PROC(a0, b0, k);
        PROC(a1, b1, k + 8);
    }
    if (k < nquads) {
        const float4 a0 = bx[32 * k];
        const float4 b0 = by[32 * k];
        PROC(a0, b0, k);
    }

    // last chunk zeroes the pad words [1900,1920)
    if (c == NCHUNK - 1 && tid < WSTRIDE - WORDS)
        g_bits[n * WSTRIDE + WORDS + tid] = 0u;

    // block reduction (8 warps, two floats)
    __shared__ float s_sum[8];
    __shared__ float s_area[8];
#pragma unroll
    for (int off = 16; off > 0; off >>= 1) {
        ssum  += __shfl_down_sync(0xffffffffu, ssum,  off);
        areaf += __shfl_down_sync(0xffffffffu, areaf, off);
    }
    if (lane == 0) { s_sum[warp] = ssum; s_area[warp] = areaf; }
    __syncthreads();
    if (tid == 0) {
        float tsum = 0.0f, tarea = 0.0f;
#pragma unroll
        for (int q = 0; q < 8; q++) { tsum += s_sum[q]; tarea += s_area[q]; }
        g_part[n * NCHUNK + c] = tsum;       // single writer: deterministic
        atomicAdd(&g_areaf[n], tarea);       // exact int-valued float: order-invariant
    }
}

// ============================================================
// Kernel 2: popc with CTA-local pair building (1216 CTAs = 1 wave).
// ============================================================
__global__ __launch_bounds__(256) void popc_kernel(const int* __restrict__ labels)
{
    __shared__ int s_lab[NN];
    __shared__ unsigned s_pairs[LMAX];
    __shared__ int s_cnt;
    const int tid  = threadIdx.x;
    const int lane = tid & 31;
    const int warp = tid >> 5;

    if (tid == 0) s_cnt = 0;
    for (int q = tid; q < NN; q += 256) s_lab[q] = labels[q];
    __syncthreads();

    const int lo = blockIdx.x * CELLS_PER_CTA;
    const int hi = min(lo + CELLS_PER_CTA, NN * NN);

    // phase 1: thread-granular label gate (<1 iteration)
    for (int p = lo + tid; p < hi; p += 256) {
        const int i = p / NN;
        const int j = p - i * NN;
        if (j > i && s_lab[i] == s_lab[j]) {
            int pos = atomicAdd(&s_cnt, 1);
            s_pairs[pos] = ((unsigned)i << 16) | (unsigned)j;
        }
    }
    __syncthreads();
    const int cnt = s_cnt;

    // phase 2: warp per pair
    for (int q = warp; q < cnt; q += 8) {
        const unsigned ij = s_pairs[q];
        const int i = (int)(ij >> 16);
        const int j = (int)(ij & 0xffffu);

        const uint4* __restrict__ bi = reinterpret_cast<const uint4*>(g_bits + i * WSTRIDE);
        const uint4* __restrict__ bj = reinterpret_cast<const uint4*>(g_bits + j * WSTRIDE);

        int inter = 0;
#pragma unroll 5
        for (int w = lane; w < WSTRIDE / 4; w += 32) {   // 15 iterations
            uint4 a = bi[w];
            uint4 b = bj[w];
            inter += __popc(a.x & b.x) + __popc(a.y & b.y)
                   + __popc(a.z & b.z) + __popc(a.w & b.w);
        }
#pragma unroll
        for (int off = 16; off > 0; off >>= 1)
            inter += __shfl_down_sync(0xffffffffu, inter, off);

        if (lane == 0) {
            float uni = g_areaf[i] + g_areaf[j] - (float)inter;
            float iou = (float)inter / fmaxf(uni, 1e-6f);
            atomicMax(reinterpret_cast<int*>(&g_comp[j]), __float_as_int(iou)); // iou>=0
            int pos = atomicAdd(&g_npairs, 1);
            g_pair_ij[pos] = ij;
            g_pair_d[pos] = iou;
        }
    }
}

// ============================================================
// Kernel 3 (single block, tiny data): scores + decay + output + reset.
// ============================================================
__global__ __launch_bounds__(1024) void decayfinal_kernel(
    const float* __restrict__ cate_scores,
    float* __restrict__ out)
{
    __shared__ float s_coef[NN];
    __shared__ float s_score[NN];
    const int tid = threadIdx.x;

    // phase 1: fixed-order reduce of chunk partials per mask
    for (int n = tid; n < NN; n += 1024) {
        float acc = 0.0f;
#pragma unroll
        for (int k = 0; k < NCHUNK; k++) acc += g_part[n * NCHUNK + k];
        s_score[n] = cate_scores[n] * (acc / fmaxf(g_areaf[n], 1.0f));
        s_coef[n] = 1.0f;
    }
    __syncthreads();

    // phase 2: decay terms -> order-independent min into smem coef
    const int np = g_npairs;
    for (int p = tid; p < np; p += 1024) {
        const unsigned ij = g_pair_ij[p];
        const int i = (int)(ij >> 16);
        const int j = (int)(ij & 0xffffu);
        const float d = g_pair_d[p];
        const float c = g_comp[i];
        const float term = __expf(SIGMA * (c * c - d * d));   // > 0
        atomicMin(reinterpret_cast<int*>(&s_coef[j]), __float_as_int(term));
    }
    __syncthreads();

    // phase 3: output + reset accumulators for next replay
    for (int n = tid; n < NN; n += 1024) {
        out[n] = s_score[n] * fminf(s_coef[n], 1.0f);
        g_areaf[n] = 0.0f;
        g_comp[n] = 0.0f;
    }
    if (tid == 0) g_npairs = 0;
}

extern "C" void kernel_launch(void* const* d_in, const int* in_sizes, int n_in,
                              void* d_out, int out_size)
{
    const float* cate_scores = (const float*)d_in[0];
    const float* segx        = (const float*)d_in[1];
    const float* segy        = (const float*)d_in[2];
    const int*   labels      = (const int*)d_in[3];
    const int*   x_inds      = (const int*)d_in[4];
    const int*   y_inds      = (const int*)d_in[5];
    float* out = (float*)d_out;

    decode_kernel<<<NN * NCHUNK, 256>>>(segx, segy, x_inds, y_inds);
    popc_kernel<<<POPC_BLOCKS, 256>>>(labels);
    decayfinal_kernel<<<1, 1024>>>(cate_scores, out);
}